// round 8
// baseline (speedup 1.0000x reference)
#include <cuda_runtime.h>
#include <cuda_bf16.h>
#include <cstdint>

// ContrastiveLoss: N=8192, D=256, 64 classes, T=0.5.
// loss = sum_i [ P_i*(2 + log denom_i) - possum_i ] / n_pos
//   denom_i  = sum_{j!=i} exp(sim_ij - 2)   (shift-invariant; sim<=2, unit-norm)
//   possum_i = sum_{j: lab_j==lab_i, j!=i} sim_ij
// R7: persistent CTAs over upper-tri tiles, FP8 e4m3 mma.sync GEMM,
// cross-tile B prefetch + A reuse along tile rows, finalize fused via
// completion counter (last CTA reduces; counters self-reset for graph replay).

#define N_ROWS 8192
#define DIM    256                     // fp8 elements per row (= 256 bytes)
#define DIMH   128                     // b16 (fp8-pair) units per row
#define NCLS   64
#define BM     128
#define BN     128
#define SSTRIDE 136                    // b16 units per smem row (128 + 8 pad)
#define NB     (N_ROWS / BM)           // 64
#define NTILES (NB * (NB + 1) / 2)     // 2080
#define GRID   296                     // persistent CTAs (<= 2 per SM on 148+)
#define NTHR   256
#define TILEB  (BM * SSTRIDE * 2)      // 34816 bytes per tile

__device__ float   g_denom[N_ROWS];
__device__ float   g_pos[N_ROWS];
__device__ uint8_t g_E8[N_ROWS * DIM];
__device__ int     g_done = 0;         // completion counter (reset by finalizer)

__device__ __forceinline__ uint32_t smem_u32(const void* p) {
    uint32_t a;
    asm("{ .reg .u64 t; cvta.to.shared.u64 t, %1; cvt.u32.u64 %0, t; }" : "=r"(a) : "l"(p));
    return a;
}
__device__ __forceinline__ void ldsm_x4(uint32_t& r0, uint32_t& r1, uint32_t& r2, uint32_t& r3,
                                        uint32_t addr) {
    asm volatile("ldmatrix.sync.aligned.m8n8.x4.shared.b16 {%0,%1,%2,%3}, [%4];"
                 : "=r"(r0), "=r"(r1), "=r"(r2), "=r"(r3) : "r"(addr));
}
__device__ __forceinline__ void mma_fp8(float* d, const uint32_t* a, uint32_t b0, uint32_t b1) {
    asm volatile(
        "mma.sync.aligned.m16n8k32.row.col.f32.e4m3.e4m3.f32 "
        "{%0,%1,%2,%3}, {%4,%5,%6,%7}, {%8,%9}, {%0,%1,%2,%3};"
        : "+f"(d[0]), "+f"(d[1]), "+f"(d[2]), "+f"(d[3])
        : "r"(a[0]), "r"(a[1]), "r"(a[2]), "r"(a[3]), "r"(b0), "r"(b1));
}
#define CP_ASYNC16(sm, gp) asm volatile("cp.async.cg.shared.global [%0], [%1], 16;" :: "r"(sm), "l"(gp) : "memory")
#define CP_COMMIT()        asm volatile("cp.async.commit_group;" ::: "memory")
#define CP_WAIT0()         asm volatile("cp.async.wait_group 0;" ::: "memory")

// ---- label width detection: int64 labels (<64) have zero high words ----
__device__ __forceinline__ int detect_is64(const int* L) {
    int s = 0;
#pragma unroll
    for (int k = 0; k < 64; k++) s |= L[2 * k + 1];
    return (s == 0) ? 1 : 0;
}
__device__ __forceinline__ int get_label(const int* L, int i, int is64) {
    return is64 ? L[2 * i] : L[i];
}

// ---- prep: zero accumulators + convert E to fp8 e4m3 ----
__global__ void prep_kernel(const float* __restrict__ E) {
    int i = blockIdx.x * blockDim.x + threadIdx.x;   // one float4 -> 4 fp8
    if (i < N_ROWS) { g_denom[i] = 0.f; g_pos[i] = 0.f; }
    float4 v = ((const float4*)E)[i];
    uint16_t h0, h1;
    asm("cvt.rn.satfinite.e4m3x2.f32 %0, %1, %2;" : "=h"(h0) : "f"(v.y), "f"(v.x));
    asm("cvt.rn.satfinite.e4m3x2.f32 %0, %1, %2;" : "=h"(h1) : "f"(v.w), "f"(v.z));
    ((uint32_t*)g_E8)[i] = (uint32_t)h0 | ((uint32_t)h1 << 16);
}

// ---- persistent: FP8 GEMM tiles + dual epilogue + fused finalize ----
// smem: A tile (persistent across a row-run) | B stage 0 | B stage 1
__global__ __launch_bounds__(NTHR, 2)
void sim_kernel(const int* __restrict__ Lraw, float* __restrict__ out) {
    extern __shared__ __align__(16) char smem[];
    __shared__ int    labI[BM], labJ[BN];
    __shared__ float  redD[BM], redP[BM], redDc[BN], redPc[BN];
    __shared__ int    cnt[NCLS];
    __shared__ double dred[NTHR];
    __shared__ int    s_is64, s_last;

    const int tid  = threadIdx.x;
    const int wid  = tid >> 5, lane = tid & 31;
    const int wm   = wid >> 2, wn = wid & 3;          // 2x4 warp grid
    const uint32_t sbase = smem_u32(smem);

    if (tid == 0) s_is64 = detect_is64(Lraw);
    __syncthreads();
    const int is64 = s_is64;

    // contiguous tile range for this CTA (upper-tri row-major order)
    const int t0 = (int)((long long)blockIdx.x * NTILES / GRID);
    const int t1 = (int)((long long)(blockIdx.x + 1) * NTILES / GRID);

    int bi = 0;
    while ((bi + 1) * NB - ((bi + 1) * bi) / 2 <= t0) bi++;
    int bj = bi + (t0 - (bi * NB - (bi * (bi - 1)) / 2));

    // async loader of one 128x256B fp8 tile into padded smem
    auto load_tile = [&](uint32_t soff, int grow) {
        const uint8_t* g = g_E8 + (size_t)grow * DIM;
#pragma unroll
        for (int u = 0; u < 8; u++) {
            int idx = tid + u * NTHR;                  // 0..2047 16B units
            int r = idx >> 4, c16 = idx & 15;
            CP_ASYNC16(sbase + soff + (uint32_t)(r * (SSTRIDE * 2) + c16 * 16),
                       g + (size_t)r * DIM + c16 * 16);
        }
    };
    auto bstage = [&](int t) { return (uint32_t)(TILEB + (t & 1) * TILEB); };

    // fragment address components (b16-unit coords; x2 for bytes)
    const uint32_t aRow = (uint32_t)(wm * 64 + (lane & 15));
    const uint32_t aKof = (uint32_t)((lane >> 4) * 8);
    const uint32_t bRow = (uint32_t)(wn * 32 + (lane & 7) + ((lane >> 4) << 3));
    const uint32_t bKof = (uint32_t)(((lane >> 3) & 1) * 8);

    if (t0 < t1) {                                     // bootstrap loads
        load_tile(0, bi * BM);
        load_tile(bstage(t0), bj * BN);
        CP_COMMIT();
    }
    int curA = bi;

    for (int t = t0; t < t1; t++) {
        const int row0 = bi * BM, col0 = bj * BN;
        const bool offdiag = (bi != bj);

        CP_WAIT0();
        __syncthreads();                               // tiles ready; red/lab reusable

        if (tid < BM) {
            labI[tid] = get_label(Lraw, row0 + tid, is64);
            labJ[tid] = get_label(Lraw, col0 + tid, is64);
            redD[tid] = 0.f; redP[tid] = 0.f; redDc[tid] = 0.f; redPc[tid] = 0.f;
        }

        int nbi = bi, nbj = bj + 1;
        if (nbj == NB) { nbi = bi + 1; nbj = nbi; }
        const bool havenext = (t + 1 < t1);
        if (havenext) { load_tile(bstage(t + 1), nbj * BN); CP_COMMIT(); }  // prefetch B

        // ---- mainloop: 8 k-steps of k32 fp8, full K resident ----
        float acc[4][4][4];
#pragma unroll
        for (int mf = 0; mf < 4; mf++)
#pragma unroll
            for (int nf = 0; nf < 4; nf++)
#pragma unroll
                for (int e = 0; e < 4; e++) acc[mf][nf][e] = 0.f;

        const uint32_t stB = sbase + bstage(t);
#pragma unroll
        for (int ks = 0; ks < DIMH / 16; ks++) {
            const uint32_t k0 = ks * 16;
            uint32_t a[4][4], b[2][4];
#pragma unroll
            for (int mf = 0; mf < 4; mf++)
                ldsm_x4(a[mf][0], a[mf][1], a[mf][2], a[mf][3],
                        sbase + ((aRow + mf * 16) * SSTRIDE + k0 + aKof) * 2u);
#pragma unroll
            for (int nb = 0; nb < 2; nb++)
                ldsm_x4(b[nb][0], b[nb][1], b[nb][2], b[nb][3],
                        stB + ((bRow + nb * 16) * SSTRIDE + k0 + bKof) * 2u);
#pragma unroll
            for (int mf = 0; mf < 4; mf++)
#pragma unroll
                for (int nf = 0; nf < 4; nf++)
                    mma_fp8(acc[mf][nf], a[mf], b[nf >> 1][(nf & 1) * 2],
                            b[nf >> 1][(nf & 1) * 2 + 1]);
        }
        __syncthreads();                               // all warps done reading A/B

        if (havenext && nbi != curA) {                 // A changes: load over epilogue
            load_tile(0, nbi * BM);
            CP_COMMIT();
            curA = nbi;
        }

        // ---- single-pass epilogue: one exp feeds row AND col sums ----
        const int rbase = wm * 64 + (lane >> 2);
        int li[8];
#pragma unroll
        for (int mf = 0; mf < 4; mf++)
#pragma unroll
            for (int h = 0; h < 2; h++) li[mf * 2 + h] = labI[rbase + mf * 16 + 8 * h];

        float dR[8], pR[8];
#pragma unroll
        for (int x = 0; x < 8; x++) { dR[x] = 0.f; pR[x] = 0.f; }

#pragma unroll
        for (int nf = 0; nf < 4; nf++) {
#pragma unroll
            for (int e = 0; e < 2; e++) {
                const int cloc = wn * 32 + nf * 8 + 2 * (lane & 3) + e;
                const int lj = labJ[cloc];
                float dc = 0.f, pc = 0.f;
#pragma unroll
                for (int mf = 0; mf < 4; mf++) {
#pragma unroll
                    for (int h = 0; h < 2; h++) {
                        const int idx = mf * 2 + h;
                        const int rloc = rbase + mf * 16 + 8 * h;
                        const float s = 2.0f * acc[mf][nf][h * 2 + e];   // /TEMPERATURE
                        const float ex = __expf(s - 2.0f);
                        const bool self = (!offdiag) && (rloc == cloc);
                        const bool eq = (li[idx] == lj);
                        if (!self) {
                            dR[idx] += ex;
                            if (eq) pR[idx] += s;
                            dc += ex;
                            if (eq) pc += s;
                        }
                    }
                }
                if (offdiag) {
                    dc += __shfl_xor_sync(0xFFFFFFFF, dc, 4);
                    dc += __shfl_xor_sync(0xFFFFFFFF, dc, 8);
                    dc += __shfl_xor_sync(0xFFFFFFFF, dc, 16);
                    pc += __shfl_xor_sync(0xFFFFFFFF, pc, 4);
                    pc += __shfl_xor_sync(0xFFFFFFFF, pc, 8);
                    pc += __shfl_xor_sync(0xFFFFFFFF, pc, 16);
                    if ((lane >> 2) == 0) {
                        atomicAdd(&redDc[cloc], dc);
                        atomicAdd(&redPc[cloc], pc);
                    }
                }
            }
        }
#pragma unroll
        for (int x = 0; x < 8; x++) {
            float d = dR[x], p = pR[x];
            d += __shfl_xor_sync(0xFFFFFFFF, d, 1);
            d += __shfl_xor_sync(0xFFFFFFFF, d, 2);
            p += __shfl_xor_sync(0xFFFFFFFF, p, 1);
            p += __shfl_xor_sync(0xFFFFFFFF, p, 2);
            if ((lane & 3) == 0) {
                const int rloc = rbase + (x >> 1) * 16 + 8 * (x & 1);
                atomicAdd(&redD[rloc], d);
                atomicAdd(&redP[rloc], p);
            }
        }

        __syncthreads();
        if (tid < BM) {
            atomicAdd(&g_denom[row0 + tid], redD[tid]);
            atomicAdd(&g_pos[row0 + tid],   redP[tid]);
            if (offdiag) {
                atomicAdd(&g_denom[col0 + tid], redDc[tid]);
                atomicAdd(&g_pos[col0 + tid],   redPc[tid]);
            }
        }
        bi = nbi; bj = nbj;
    }

    // ---- completion: last CTA runs the finalize reduction ----
    __threadfence();
    __syncthreads();
    if (tid == 0) s_last = (atomicAdd(&g_done, 1) == GRID - 1) ? 1 : 0;
    __syncthreads();
    if (s_last) {
        __threadfence();
        if (tid < NCLS) cnt[tid] = 0;
        __syncthreads();
        for (int i = tid; i < N_ROWS; i += NTHR)
            atomicAdd(&cnt[get_label(Lraw, i, is64)], 1);
        __syncthreads();
        double acc = 0.0;
        for (int i = tid; i < N_ROWS; i += NTHR) {
            int P = cnt[get_label(Lraw, i, is64)] - 1;
            float dn = __ldcg(&g_denom[i]);           // bypass stale L1
            float ps = __ldcg(&g_pos[i]);
            acc += (double)P * (2.0 + (double)logf(dn)) - (double)ps;
        }
        dred[tid] = acc;
        __syncthreads();
        for (int s = 128; s > 0; s >>= 1) {
            if (tid < s) dred[tid] += dred[tid + s];
            __syncthreads();
        }
        if (tid == 0) {
            long long npos = 0;
            for (int c = 0; c < NCLS; c++)
                npos += (long long)cnt[c] * (long long)(cnt[c] - 1);
            out[0] = (float)(dred[0] / (double)npos);
            g_done = 0;                                // reset for next graph replay
        }
    }
}

extern "C" void kernel_launch(void* const* d_in, const int* in_sizes, int n_in,
                              void* d_out, int out_size) {
    const float* E    = (const float*)d_in[0];
    const int*   Lraw = (const int*)d_in[1];   // width auto-detected on device
    float* out = (float*)d_out;

    const int DYN_SMEM = 3 * TILEB;            // A + B0 + B1 = 104448 bytes
    cudaFuncSetAttribute(sim_kernel, cudaFuncAttributeMaxDynamicSharedMemorySize, DYN_SMEM);

    prep_kernel<<<(N_ROWS * DIM / 4) / 256, 256>>>(E);
    sim_kernel<<<GRID, NTHR, DYN_SMEM>>>(Lraw, out);
}

// round 9
// speedup vs baseline: 1.4167x; 1.4167x over previous
#include <cuda_runtime.h>
#include <cuda_bf16.h>
#include <cstdint>

// ContrastiveLoss: N=8192, D=256, 64 classes, T=0.5.
// loss = sum_i [ P_i*(2 + log denom_i) - possum_i ] / n_pos
//   denom_i  = sum_{j!=i} exp(sim_ij - 2)   (shift-invariant; sim<=2, unit-norm)
//   possum_i = sum_{j: lab_j==lab_i, j!=i} sim_ij
// R8: grid-per-tile (R6 structure, proven), FP8 e4m3 mma.sync, BN=64 tiles ->
// 4 independent CTAs/SM for cross-CTA phase overlap. Uniform triangle rule:
// tiles cb >= 2*bi, element included iff gj > gi, dual row+col accumulation.

#define N_ROWS 8192
#define DIM    256                     // fp8 elements per row (= 256 bytes)
#define DIMH   128                     // b16 (fp8-pair) units per row
#define NCLS   64
#define BM     128
#define BN     64
#define SSTRIDE 136                    // b16 units per smem row (128 + 8 pad)
#define SROWB  (SSTRIDE * 2)           // 272 bytes per smem row
#define ABYTES (BM * SROWB)            // 34816
#define NBR    (N_ROWS / BM)           // 64 row blocks
#define NTILES 4160                    // sum_{bi}(128 - 2*bi)
#define NTHR   128

__device__ float   g_denom[N_ROWS];
__device__ float   g_pos[N_ROWS];
__device__ uint8_t g_E8[N_ROWS * DIM];

__device__ __forceinline__ uint32_t smem_u32(const void* p) {
    uint32_t a;
    asm("{ .reg .u64 t; cvta.to.shared.u64 t, %1; cvt.u32.u64 %0, t; }" : "=r"(a) : "l"(p));
    return a;
}
__device__ __forceinline__ void ldsm_x4(uint32_t& r0, uint32_t& r1, uint32_t& r2, uint32_t& r3,
                                        uint32_t addr) {
    asm volatile("ldmatrix.sync.aligned.m8n8.x4.shared.b16 {%0,%1,%2,%3}, [%4];"
                 : "=r"(r0), "=r"(r1), "=r"(r2), "=r"(r3) : "r"(addr));
}
__device__ __forceinline__ void mma_fp8(float* d, const uint32_t* a, uint32_t b0, uint32_t b1) {
    asm volatile(
        "mma.sync.aligned.m16n8k32.row.col.f32.e4m3.e4m3.f32 "
        "{%0,%1,%2,%3}, {%4,%5,%6,%7}, {%8,%9}, {%0,%1,%2,%3};"
        : "+f"(d[0]), "+f"(d[1]), "+f"(d[2]), "+f"(d[3])
        : "r"(a[0]), "r"(a[1]), "r"(a[2]), "r"(a[3]), "r"(b0), "r"(b1));
}
__device__ __forceinline__ float ex2f(float x) {
    float y;
    asm("ex2.approx.f32 %0, %1;" : "=f"(y) : "f"(x));
    return y;
}
#define CP_ASYNC16(sm, gp) asm volatile("cp.async.cg.shared.global [%0], [%1], 16;" :: "r"(sm), "l"(gp) : "memory")
#define CP_COMMIT()        asm volatile("cp.async.commit_group;" ::: "memory")
#define CP_WAIT0()         asm volatile("cp.async.wait_group 0;" ::: "memory")

// ---- label width detection: int64 labels (<64) have zero high words ----
__device__ __forceinline__ int detect_is64(const int* L) {
    int s = 0;
#pragma unroll
    for (int k = 0; k < 64; k++) s |= L[2 * k + 1];
    return (s == 0) ? 1 : 0;
}
__device__ __forceinline__ int get_label(const int* L, int i, int is64) {
    return is64 ? L[2 * i] : L[i];
}

// ---- prep: zero accumulators + convert E to fp8 e4m3 ----
__global__ void prep_kernel(const float* __restrict__ E) {
    int i = blockIdx.x * blockDim.x + threadIdx.x;   // one float4 -> 4 fp8
    if (i < N_ROWS) { g_denom[i] = 0.f; g_pos[i] = 0.f; }
    float4 v = ((const float4*)E)[i];
    uint16_t h0, h1;
    asm("cvt.rn.satfinite.e4m3x2.f32 %0, %1, %2;" : "=h"(h0) : "f"(v.y), "f"(v.x));
    asm("cvt.rn.satfinite.e4m3x2.f32 %0, %1, %2;" : "=h"(h1) : "f"(v.w), "f"(v.z));
    ((uint32_t*)g_E8)[i] = (uint32_t)h0 | ((uint32_t)h1 << 16);
}

// ---- fused FP8 GEMM + dual epilogue; 128x64 tiles, 4 warps (2x2) ----
__global__ __launch_bounds__(NTHR, 4)
void sim_kernel(const int* __restrict__ Lraw) {
    extern __shared__ __align__(16) char smem[];   // A[128][272B] | B[64][272B]
    __shared__ int   labI[BM], labJ[BN];
    __shared__ float redD[BM], redP[BM], redDc[BN], redPc[BN];
    __shared__ int   s_is64;

    const int tid  = threadIdx.x;
    const int wid  = tid >> 5, lane = tid & 31;
    const int wm   = wid >> 1, wn = wid & 1;          // 2x2 warp grid

    // ---- tile id -> (bi, cb): tiles with cb >= 2*bi; offset(bi)=bi*(129-bi) ----
    const int t = blockIdx.x;
    int bi = (int)((129.0f - sqrtf(16641.0f - 4.0f * (float)t)) * 0.5f);
    while (bi > 0 && bi * (129 - bi) > t) bi--;
    while ((bi + 1) * (129 - (bi + 1)) <= t) bi++;
    const int cb = 2 * bi + (t - bi * (129 - bi));
    const int row0 = bi * BM, col0 = cb * BN;

    const uint32_t sbase = smem_u32(smem);
    const uint32_t stB = sbase + ABYTES;

    if (tid == 0) s_is64 = detect_is64(Lraw);
    if (tid < BM) { redD[tid] = 0.f; redP[tid] = 0.f; }
    if (tid < BN) { redDc[tid] = 0.f; redPc[tid] = 0.f; }

    // ---- one-shot async load: A 128x256B, B 64x256B ----
    {
        const uint8_t* gA = g_E8 + (size_t)row0 * DIM;
        const uint8_t* gB = g_E8 + (size_t)col0 * DIM;
#pragma unroll
        for (int u = 0; u < 16; u++) {
            int idx = tid + u * NTHR;                  // 0..2047 16B units
            int r = idx >> 4, c16 = idx & 15;
            CP_ASYNC16(sbase + (uint32_t)(r * SROWB + c16 * 16),
                       gA + (size_t)r * DIM + c16 * 16);
        }
#pragma unroll
        for (int u = 0; u < 8; u++) {
            int idx = tid + u * NTHR;                  // 0..1023 16B units
            int r = idx >> 4, c16 = idx & 15;
            CP_ASYNC16(stB + (uint32_t)(r * SROWB + c16 * 16),
                       gB + (size_t)r * DIM + c16 * 16);
        }
        CP_COMMIT();
    }

    float acc[4][4][4];
#pragma unroll
    for (int mf = 0; mf < 4; mf++)
#pragma unroll
        for (int nf = 0; nf < 4; nf++)
#pragma unroll
            for (int e = 0; e < 4; e++) acc[mf][nf][e] = 0.f;

    __syncthreads();                                   // publish s_is64 / red zeros
    if (tid < BM) labI[tid] = get_label(Lraw, row0 + tid, s_is64);
    if (tid < BN) labJ[tid] = get_label(Lraw, col0 + tid, s_is64);

    // fragment address components (b16-unit coords; x2 for bytes)
    const uint32_t aRow = (uint32_t)(wm * 64 + (lane & 15));
    const uint32_t aKof = (uint32_t)((lane >> 4) * 8);
    const uint32_t bRow = (uint32_t)(wn * 32 + (lane & 7) + ((lane >> 4) << 3));
    const uint32_t bKof = (uint32_t)(((lane >> 3) & 1) * 8);

    CP_WAIT0();
    __syncthreads();

    // ---- mainloop: 8 k-steps of k32 fp8, full K resident, no syncs ----
#pragma unroll
    for (int ks = 0; ks < DIMH / 16; ks++) {
        const uint32_t k0 = ks * 16;
        uint32_t a[4][4], b[2][4];
#pragma unroll
        for (int mf = 0; mf < 4; mf++)
            ldsm_x4(a[mf][0], a[mf][1], a[mf][2], a[mf][3],
                    sbase + ((aRow + mf * 16) * SSTRIDE + k0 + aKof) * 2u);
#pragma unroll
        for (int nb = 0; nb < 2; nb++)
            ldsm_x4(b[nb][0], b[nb][1], b[nb][2], b[nb][3],
                    stB + ((bRow + nb * 16) * SSTRIDE + k0 + bKof) * 2u);
#pragma unroll
        for (int mf = 0; mf < 4; mf++)
#pragma unroll
            for (int nf = 0; nf < 4; nf++)
                mma_fp8(acc[mf][nf], a[mf], b[nf >> 1][(nf & 1) * 2],
                        b[nf >> 1][(nf & 1) * 2 + 1]);
    }

    // ---- epilogue: include iff gj > gi; one exp feeds row AND col sums ----
    const int rbase = wm * 64 + (lane >> 2);
    int li[8];
#pragma unroll
    for (int mf = 0; mf < 4; mf++)
#pragma unroll
        for (int h = 0; h < 2; h++) li[mf * 2 + h] = labI[rbase + mf * 16 + 8 * h];

    float dR[8], pR[8];
#pragma unroll
    for (int x = 0; x < 8; x++) { dR[x] = 0.f; pR[x] = 0.f; }

    const float L2E = 1.4426950408889634f;
    const float C2  = -2.8853900817779268f;            // -2*log2(e)

#pragma unroll
    for (int nf = 0; nf < 4; nf++) {
#pragma unroll
        for (int e = 0; e < 2; e++) {
            const int cloc = wn * 32 + nf * 8 + 2 * (lane & 3) + e;
            const int gj = col0 + cloc;
            const int lj = labJ[cloc];
            float dc = 0.f, pc = 0.f;
#pragma unroll
            for (int mf = 0; mf < 4; mf++) {
#pragma unroll
                for (int h = 0; h < 2; h++) {
                    const int idx = mf * 2 + h;
                    const int gi = row0 + rbase + mf * 16 + 8 * h;
                    const float s = acc[mf][nf][h * 2 + e] + acc[mf][nf][h * 2 + e]; // 2*acc
                    const float ex = ex2f(fmaf(s, L2E, C2));       // exp(s-2)
                    if (gj > gi) {
                        dR[idx] += ex;
                        dc += ex;
                        if (li[idx] == lj) { pR[idx] += s; pc += s; }
                    }
                }
            }
            dc += __shfl_xor_sync(0xFFFFFFFF, dc, 4);
            dc += __shfl_xor_sync(0xFFFFFFFF, dc, 8);
            dc += __shfl_xor_sync(0xFFFFFFFF, dc, 16);
            pc += __shfl_xor_sync(0xFFFFFFFF, pc, 4);
            pc += __shfl_xor_sync(0xFFFFFFFF, pc, 8);
            pc += __shfl_xor_sync(0xFFFFFFFF, pc, 16);
            if ((lane >> 2) == 0) {
                atomicAdd(&redDc[cloc], dc);
                atomicAdd(&redPc[cloc], pc);
            }
        }
    }
#pragma unroll
    for (int x = 0; x < 8; x++) {
        float d = dR[x], p = pR[x];
        d += __shfl_xor_sync(0xFFFFFFFF, d, 1);
        d += __shfl_xor_sync(0xFFFFFFFF, d, 2);
        p += __shfl_xor_sync(0xFFFFFFFF, p, 1);
        p += __shfl_xor_sync(0xFFFFFFFF, p, 2);
        if ((lane & 3) == 0) {
            const int rloc = rbase + (x >> 1) * 16 + 8 * (x & 1);
            atomicAdd(&redD[rloc], d);
            atomicAdd(&redP[rloc], p);
        }
    }

    __syncthreads();
    if (tid < BM) {
        atomicAdd(&g_denom[row0 + tid], redD[tid]);
        atomicAdd(&g_pos[row0 + tid],   redP[tid]);
    }
    if (tid < BN) {
        atomicAdd(&g_denom[col0 + tid], redDc[tid]);
        atomicAdd(&g_pos[col0 + tid],   redPc[tid]);
    }
}

// ---- finalize: label histogram, per-row combine, scalar loss ----
__global__ void finalize_kernel(const int* __restrict__ Lraw, float* __restrict__ out) {
    __shared__ int cnt[NCLS];
    __shared__ double red[256];
    __shared__ int s_is64;
    const int tid = threadIdx.x;

    if (tid == 0) s_is64 = detect_is64(Lraw);
    if (tid < NCLS) cnt[tid] = 0;
    __syncthreads();
    const int is64 = s_is64;

    for (int i = tid; i < N_ROWS; i += 256)
        atomicAdd(&cnt[get_label(Lraw, i, is64)], 1);
    __syncthreads();

    double acc = 0.0;
    for (int i = tid; i < N_ROWS; i += 256) {
        int P = cnt[get_label(Lraw, i, is64)] - 1;
        acc += (double)P * (2.0 + (double)logf(g_denom[i])) - (double)g_pos[i];
    }
    red[tid] = acc;
    __syncthreads();
    for (int s = 128; s > 0; s >>= 1) {
        if (tid < s) red[tid] += red[tid + s];
        __syncthreads();
    }
    if (tid == 0) {
        long long npos = 0;
        for (int c = 0; c < NCLS; c++)
            npos += (long long)cnt[c] * (long long)(cnt[c] - 1);
        out[0] = (float)(red[0] / (double)npos);
    }
}

extern "C" void kernel_launch(void* const* d_in, const int* in_sizes, int n_in,
                              void* d_out, int out_size) {
    const float* E    = (const float*)d_in[0];
    const int*   Lraw = (const int*)d_in[1];   // width auto-detected on device
    float* out = (float*)d_out;

    const int DYN_SMEM = (BM + BN) * SROWB;    // 52224 bytes -> 4 CTAs/SM
    cudaFuncSetAttribute(sim_kernel, cudaFuncAttributeMaxDynamicSharedMemorySize, DYN_SMEM);

    prep_kernel<<<(N_ROWS * DIM / 4) / 256, 256>>>(E);
    sim_kernel<<<NTILES, NTHR, DYN_SMEM>>>(Lraw);
    finalize_kernel<<<1, 256>>>(Lraw, out);
}

// round 10
// speedup vs baseline: 1.4566x; 1.0281x over previous
#include <cuda_runtime.h>
#include <cuda_bf16.h>
#include <cstdint>

// ContrastiveLoss: N=8192, D=256, 64 classes, T=0.5.
// loss = sum_i [ P_i*(2 + log denom_i) - possum_i ] / n_pos
//   denom_i  = sum_{j!=i} exp(sim_ij - 2)   (shift-invariant; sim<=2, unit-norm)
//   possum_i = sum_{j: lab_j==lab_i, j!=i} sim_ij
// R9 = R6 champion structure (FP8 e4m3 mma.sync, 128x128 tiles, grid-per-tile,
// upper-tri + dual row/col epilogue) + split-K load pipeline (2 cp.async
// groups, mainloop starts after half) + finalize fused via completion counter.

#define N_ROWS 8192
#define DIM    256                     // fp8 elements per row (= 256 bytes)
#define DIMH   128                     // b16 (fp8-pair) units per row
#define NCLS   64
#define BM     128
#define BN     128
#define SSTRIDE 136                    // b16 units per smem row (128 + 8 pad)
#define SROWB  (SSTRIDE * 2)           // 272 bytes per smem row
#define NB     (N_ROWS / BM)           // 64
#define NTILES (NB * (NB + 1) / 2)     // 2080 upper-tri tiles
#define NTHR   256

__device__ float   g_denom[N_ROWS];
__device__ float   g_pos[N_ROWS];
__device__ uint8_t g_E8[N_ROWS * DIM];
__device__ int     g_done = 0;         // completion counter (self-resetting)

__device__ __forceinline__ uint32_t smem_u32(const void* p) {
    uint32_t a;
    asm("{ .reg .u64 t; cvta.to.shared.u64 t, %1; cvt.u32.u64 %0, t; }" : "=r"(a) : "l"(p));
    return a;
}
__device__ __forceinline__ void ldsm_x4(uint32_t& r0, uint32_t& r1, uint32_t& r2, uint32_t& r3,
                                        uint32_t addr) {
    asm volatile("ldmatrix.sync.aligned.m8n8.x4.shared.b16 {%0,%1,%2,%3}, [%4];"
                 : "=r"(r0), "=r"(r1), "=r"(r2), "=r"(r3) : "r"(addr));
}
__device__ __forceinline__ void mma_fp8(float* d, const uint32_t* a, uint32_t b0, uint32_t b1) {
    asm volatile(
        "mma.sync.aligned.m16n8k32.row.col.f32.e4m3.e4m3.f32 "
        "{%0,%1,%2,%3}, {%4,%5,%6,%7}, {%8,%9}, {%0,%1,%2,%3};"
        : "+f"(d[0]), "+f"(d[1]), "+f"(d[2]), "+f"(d[3])
        : "r"(a[0]), "r"(a[1]), "r"(a[2]), "r"(a[3]), "r"(b0), "r"(b1));
}
__device__ __forceinline__ float ex2f(float x) {
    float y;
    asm("ex2.approx.f32 %0, %1;" : "=f"(y) : "f"(x));
    return y;
}
#define CP_ASYNC16(sm, gp) asm volatile("cp.async.cg.shared.global [%0], [%1], 16;" :: "r"(sm), "l"(gp) : "memory")
#define CP_COMMIT()        asm volatile("cp.async.commit_group;" ::: "memory")
#define CP_WAIT(n)         asm volatile("cp.async.wait_group %0;" :: "n"(n) : "memory")

// ---- label width detection: int64 labels (<64) have zero high words ----
__device__ __forceinline__ int detect_is64(const int* L) {
    int s = 0;
#pragma unroll
    for (int k = 0; k < 64; k++) s |= L[2 * k + 1];
    return (s == 0) ? 1 : 0;
}
__device__ __forceinline__ int get_label(const int* L, int i, int is64) {
    return is64 ? L[2 * i] : L[i];
}

// ---- prep: zero accumulators + convert E to fp8 e4m3 ----
__global__ void prep_kernel(const float* __restrict__ E) {
    int i = blockIdx.x * blockDim.x + threadIdx.x;   // one float4 -> 4 fp8
    if (i < N_ROWS) { g_denom[i] = 0.f; g_pos[i] = 0.f; }
    float4 v = ((const float4*)E)[i];
    uint16_t h0, h1;
    asm("cvt.rn.satfinite.e4m3x2.f32 %0, %1, %2;" : "=h"(h0) : "f"(v.y), "f"(v.x));
    asm("cvt.rn.satfinite.e4m3x2.f32 %0, %1, %2;" : "=h"(h1) : "f"(v.w), "f"(v.z));
    ((uint32_t*)g_E8)[i] = (uint32_t)h0 | ((uint32_t)h1 << 16);
}

// ---- fused FP8 GEMM + dual epilogue + fused finalize; upper-tri tiles ----
// 256 threads = 8 warps in 2(m) x 4(n); warp tile 64x32; full K resident.
__global__ __launch_bounds__(NTHR, 2)
void sim_kernel(const int* __restrict__ Lraw, float* __restrict__ out) {
    extern __shared__ __align__(16) char smem[];   // A[128][272B] | B[128][272B]
    __shared__ int    labI[BM], labJ[BN];
    __shared__ float  redD[BM], redP[BM], redDc[BN], redPc[BN];
    __shared__ int    cnt[NCLS];
    __shared__ double dred[NTHR];
    __shared__ int    s_is64, s_last;

    const int tid  = threadIdx.x;
    const int wid  = tid >> 5, lane = tid & 31;
    const int wm   = wid >> 2, wn = wid & 3;          // 2x4 warp grid

    // ---- linear tile id -> upper-triangular (bi, bj) ----
    const int t = blockIdx.x;
    int bi = (int)((2.0f * NB + 1.0f -
                    sqrtf((2.0f * NB + 1.0f) * (2.0f * NB + 1.0f) - 8.0f * (float)t)) * 0.5f);
    while (bi > 0 && bi * NB - bi * (bi - 1) / 2 > t) bi--;
    while ((bi + 1) * NB - (bi + 1) * bi / 2 <= t) bi++;
    const int bj = bi + (t - (bi * NB - bi * (bi - 1) / 2));
    const int row0 = bi * BM, col0 = bj * BN;
    const bool offdiag = (bi != bj);

    const uint32_t sbase = smem_u32(smem);
    const uint32_t stB = sbase + (uint32_t)(BM * SROWB);

    if (tid == 0) s_is64 = detect_is64(Lraw);
    if (tid < BM) { redD[tid] = 0.f; redP[tid] = 0.f; redDc[tid] = 0.f; redPc[tid] = 0.f; }

    // ---- split-K async load: group 1 = K bytes [0,128), group 2 = [128,256) ----
    {
        const uint8_t* gA = g_E8 + (size_t)row0 * DIM;
        const uint8_t* gB = g_E8 + (size_t)col0 * DIM;
#pragma unroll
        for (int half = 0; half < 2; half++) {
            const int cbase = half * 8;                 // 16B-chunk column base
#pragma unroll
            for (int u = 0; u < 4; u++) {
                int idx = tid + u * NTHR;               // 0..1023: row*8 + chunk
                int r = idx >> 3, c16 = cbase + (idx & 7);
                uint32_t so = (uint32_t)(r * SROWB + c16 * 16);
                const size_t go = (size_t)r * DIM + c16 * 16;
                CP_ASYNC16(sbase + so, gA + go);
                CP_ASYNC16(stB + so, gB + go);
            }
            CP_COMMIT();
        }
    }

    float acc[4][4][4];
#pragma unroll
    for (int mf = 0; mf < 4; mf++)
#pragma unroll
        for (int nf = 0; nf < 4; nf++)
#pragma unroll
            for (int e = 0; e < 4; e++) acc[mf][nf][e] = 0.f;

    __syncthreads();                                   // publish s_is64 / red zeros
    if (tid < BM) {
        labI[tid] = get_label(Lraw, row0 + tid, s_is64);
        labJ[tid] = get_label(Lraw, col0 + tid, s_is64);
    }

    // fragment address components (b16-unit coords; x2 for bytes)
    const uint32_t aRow = (uint32_t)(wm * 64 + (lane & 15));
    const uint32_t aKof = (uint32_t)((lane >> 4) * 8);
    const uint32_t bRow = (uint32_t)(wn * 32 + (lane & 7) + ((lane >> 4) << 3));
    const uint32_t bKof = (uint32_t)(((lane >> 3) & 1) * 8);

    // ---- mainloop: k-halves pipelined against the two cp.async groups ----
#pragma unroll
    for (int half = 0; half < 2; half++) {
        if (half == 0) CP_WAIT(1); else CP_WAIT(0);
        __syncthreads();
#pragma unroll
        for (int kss = 0; kss < 4; kss++) {
            const uint32_t k0 = (half * 4 + kss) * 16;
            uint32_t a[4][4], b[2][4];
#pragma unroll
            for (int mf = 0; mf < 4; mf++)
                ldsm_x4(a[mf][0], a[mf][1], a[mf][2], a[mf][3],
                        sbase + ((aRow + mf * 16) * SSTRIDE + k0 + aKof) * 2u);
#pragma unroll
            for (int nb = 0; nb < 2; nb++)
                ldsm_x4(b[nb][0], b[nb][1], b[nb][2], b[nb][3],
                        stB + ((bRow + nb * 16) * SSTRIDE + k0 + bKof) * 2u);
#pragma unroll
            for (int mf = 0; mf < 4; mf++)
#pragma unroll
                for (int nf = 0; nf < 4; nf++)
                    mma_fp8(acc[mf][nf], a[mf], b[nf >> 1][(nf & 1) * 2],
                            b[nf >> 1][(nf & 1) * 2 + 1]);
        }
    }

    // ---- single-pass epilogue: one exp per element feeds row AND col sums ----
    const int rbase = wm * 64 + (lane >> 2);
    int li[8];
#pragma unroll
    for (int mf = 0; mf < 4; mf++)
#pragma unroll
        for (int h = 0; h < 2; h++) li[mf * 2 + h] = labI[rbase + mf * 16 + 8 * h];

    float dR[8], pR[8];
#pragma unroll
    for (int x = 0; x < 8; x++) { dR[x] = 0.f; pR[x] = 0.f; }

    const float L2E = 1.4426950408889634f;
    const float C2  = -2.8853900817779268f;            // -2*log2(e)

#pragma unroll
    for (int nf = 0; nf < 4; nf++) {
#pragma unroll
        for (int e = 0; e < 2; e++) {
            const int cloc = wn * 32 + nf * 8 + 2 * (lane & 3) + e;
            const int lj = labJ[cloc];
            float dc = 0.f, pc = 0.f;
#pragma unroll
            for (int mf = 0; mf < 4; mf++) {
#pragma unroll
                for (int h = 0; h < 2; h++) {
                    const int idx = mf * 2 + h;
                    const int rloc = rbase + mf * 16 + 8 * h;
                    const float s = acc[mf][nf][h * 2 + e] + acc[mf][nf][h * 2 + e];
                    const float ex = ex2f(fmaf(s, L2E, C2));       // exp(s-2)
                    const bool self = (!offdiag) && (rloc == cloc);
                    const bool eq = (li[idx] == lj);
                    if (!self) {
                        dR[idx] += ex;
                        if (eq) pR[idx] += s;
                        dc += ex;
                        if (eq) pc += s;
                    }
                }
            }
            if (offdiag) {
                dc += __shfl_xor_sync(0xFFFFFFFF, dc, 4);
                dc += __shfl_xor_sync(0xFFFFFFFF, dc, 8);
                dc += __shfl_xor_sync(0xFFFFFFFF, dc, 16);
                pc += __shfl_xor_sync(0xFFFFFFFF, pc, 4);
                pc += __shfl_xor_sync(0xFFFFFFFF, pc, 8);
                pc += __shfl_xor_sync(0xFFFFFFFF, pc, 16);
                if ((lane >> 2) == 0) {
                    atomicAdd(&redDc[cloc], dc);
                    atomicAdd(&redPc[cloc], pc);
                }
            }
        }
    }
#pragma unroll
    for (int x = 0; x < 8; x++) {
        float d = dR[x], p = pR[x];
        d += __shfl_xor_sync(0xFFFFFFFF, d, 1);
        d += __shfl_xor_sync(0xFFFFFFFF, d, 2);
        p += __shfl_xor_sync(0xFFFFFFFF, p, 1);
        p += __shfl_xor_sync(0xFFFFFFFF, p, 2);
        if ((lane & 3) == 0) {
            const int rloc = rbase + (x >> 1) * 16 + 8 * (x & 1);
            atomicAdd(&redD[rloc], d);
            atomicAdd(&redP[rloc], p);
        }
    }

    __syncthreads();
    if (tid < BM) {
        atomicAdd(&g_denom[row0 + tid], redD[tid]);
        atomicAdd(&g_pos[row0 + tid],   redP[tid]);
        if (offdiag) {
            atomicAdd(&g_denom[col0 + tid], redDc[tid]);
            atomicAdd(&g_pos[col0 + tid],   redPc[tid]);
        }
    }

    // ---- completion: last CTA runs the finalize reduction ----
    __threadfence();
    __syncthreads();
    if (tid == 0) s_last = (atomicAdd(&g_done, 1) == NTILES - 1) ? 1 : 0;
    __syncthreads();
    if (s_last) {
        __threadfence();
        if (tid < NCLS) cnt[tid] = 0;
        __syncthreads();
        for (int i = tid; i < N_ROWS; i += NTHR)
            atomicAdd(&cnt[get_label(Lraw, i, s_is64)], 1);
        __syncthreads();
        double acc2 = 0.0;
        for (int i = tid; i < N_ROWS; i += NTHR) {
            int P = cnt[get_label(Lraw, i, s_is64)] - 1;
            float dn = __ldcg(&g_denom[i]);           // bypass stale L1
            float ps = __ldcg(&g_pos[i]);
            acc2 += (double)P * (2.0 + (double)logf(dn)) - (double)ps;
        }
        dred[tid] = acc2;
        __syncthreads();
        for (int s = 128; s > 0; s >>= 1) {
            if (tid < s) dred[tid] += dred[tid + s];
            __syncthreads();
        }
        if (tid == 0) {
            long long npos = 0;
            for (int c = 0; c < NCLS; c++)
                npos += (long long)cnt[c] * (long long)(cnt[c] - 1);
            out[0] = (float)(dred[0] / (double)npos);
            g_done = 0;                                // reset for next graph replay
        }
    }
}

extern "C" void kernel_launch(void* const* d_in, const int* in_sizes, int n_in,
                              void* d_out, int out_size) {
    const float* E    = (const float*)d_in[0];
    const int*   Lraw = (const int*)d_in[1];   // width auto-detected on device
    float* out = (float*)d_out;

    const int DYN_SMEM = 2 * BM * SROWB;       // A+B tiles, full K: 69632 B
    cudaFuncSetAttribute(sim_kernel, cudaFuncAttributeMaxDynamicSharedMemorySize, DYN_SMEM);

    prep_kernel<<<(N_ROWS * DIM / 4) / 256, 256>>>(E);
    sim_kernel<<<NTILES, NTHR, DYN_SMEM>>>(Lraw, out);
}